// round 4
// baseline (speedup 1.0000x reference)
#include <cuda_runtime.h>
#include <math.h>

// Problem constants (fixed shapes from reference setup_inputs)
#define NMAX 40000
#define EMAX 640000
#define HID  128
#define FIN  64
#define FOUT 64
#define STATS_BLOCKS 1024

// ---------------- device scratch (allocation-free: static globals) ----------------
__device__ float g_A[NMAX * HID];      // x @ W1a.T   [N,128]
__device__ float g_B[NMAX * HID];      // x @ W1b.T   [N,128]
__device__ float g_h1[NMAX * HID];     // h1 rows 0..N  (A[src]+B[dst])
__device__ float g_agg1[NMAX * HID];   // edge-aggregated h1
__device__ float g_wz[NMAX * FOUT];    // W2l @ r_j for j<N
__device__ float g_wa2[NMAX * FOUT];   // edge-aggregated wz
__device__ int   g_cnt[NMAX];
__device__ int   g_fill[NMAX];
__device__ int   g_rowptr[NMAX + 1];
__device__ int   g_eid[EMAX];
__device__ int   g_csrc[EMAX];
__device__ float g_cnorm[EMAX];
__device__ float g_dis[NMAX];
__device__ float g_invdeg[NMAX];
__device__ float g_part[STATS_BLOCKS * 2 * HID];
__device__ float g_af[HID];
__device__ float g_cf[HID];
__device__ float g_W2l[FOUT * HID];    // Wl @ W2  [64,128]
__device__ float g_cvec[FOUT];         // Wl@b2 + bl

// ---------------- kernels ----------------

__global__ void k_zero(int Ncur) {
    int t = blockIdx.x * blockDim.x + threadIdx.x;
    if (t < Ncur) { g_cnt[t] = 0; g_fill[t] = 0; }
}

__global__ void k_count(const int* __restrict__ dst, int Ecur) {
    int e = blockIdx.x * blockDim.x + threadIdx.x;
    if (e < Ecur) atomicAdd(&g_cnt[dst[e]], 1);
}

__global__ void k_dis(int Ncur) {
    int t = blockIdx.x * blockDim.x + threadIdx.x;
    if (t < Ncur) {
        float dg = (float)(g_cnt[t] + 1);
        g_dis[t]    = rsqrtf(dg);
        g_invdeg[t] = 1.0f / dg;
    }
}

// exclusive prefix sum of g_cnt -> g_rowptr (single block, chunked scan)
__global__ void k_scan(int Ncur) {
    __shared__ int sh[1024];
    int t = threadIdx.x;
    int carry = 0;
    int nchunk = (Ncur + 1023) / 1024;
    for (int c = 0; c < nchunk; c++) {
        int idx = c * 1024 + t;
        int v = (idx < Ncur) ? g_cnt[idx] : 0;
        sh[t] = v;
        __syncthreads();
        for (int off = 1; off < 1024; off <<= 1) {
            int xv = (t >= off) ? sh[t - off] : 0;
            __syncthreads();
            sh[t] += xv;
            __syncthreads();
        }
        if (idx < Ncur) g_rowptr[idx] = carry + sh[t] - v;
        carry += sh[1023];
        __syncthreads();
    }
    if (t == 0) g_rowptr[Ncur] = carry;
}

__global__ void k_fill(const int* __restrict__ dst, int Ecur) {
    int e = blockIdx.x * blockDim.x + threadIdx.x;
    if (e < Ecur) {
        int d = dst[e];
        int slot = g_rowptr[d] + atomicAdd(&g_fill[d], 1);
        g_eid[slot] = e;
    }
}

// sort each bucket by edge id (determinism), emit src + norm per slot
__global__ void k_sort(const int* __restrict__ src, int Ncur) {
    int i = blockIdx.x * blockDim.x + threadIdx.x;
    if (i >= Ncur) return;
    int lo = g_rowptr[i], hi = g_rowptr[i + 1];
    for (int a = lo + 1; a < hi; a++) {
        int key = g_eid[a];
        int b = a - 1;
        while (b >= lo && g_eid[b] > key) { g_eid[b + 1] = g_eid[b]; b--; }
        g_eid[b + 1] = key;
    }
    float di = g_dis[i];
    for (int k = lo; k < hi; k++) {
        int e = g_eid[k];
        int s = src[e];
        g_csrc[k]  = s;
        g_cnorm[k] = di * g_dis[s];
    }
}

// A = x @ W1[:, :64].T ; B = x @ W1[:, 64:].T   (16 nodes per block)
__global__ void __launch_bounds__(128) k_ab(const float* __restrict__ x,
                                            const float* __restrict__ W1, int Ncur) {
    __shared__ float xs[16][FIN];
    int j0 = blockIdx.x * 16;
    for (int idx = threadIdx.x; idx < 16 * FIN; idx += 128) {
        int j = idx >> 6, k = idx & 63;
        xs[j][k] = (j0 + j < Ncur) ? x[(j0 + j) * FIN + k] : 0.0f;
    }
    __syncthreads();
    int o = threadIdx.x;
    float accA[16], accB[16];
#pragma unroll
    for (int j = 0; j < 16; j++) { accA[j] = 0.f; accB[j] = 0.f; }
    const float* w = W1 + o * (2 * FIN);
    for (int k = 0; k < FIN; k++) {
        float wa = w[k], wb = w[FIN + k];
#pragma unroll
        for (int j = 0; j < 16; j++) {
            float xv = xs[j][k];
            accA[j] = fmaf(wa, xv, accA[j]);
            accB[j] = fmaf(wb, xv, accB[j]);
        }
    }
    for (int j = 0; j < 16; j++) {
        if (j0 + j < Ncur) {
            g_A[(j0 + j) * HID + o] = accA[j];
            g_B[(j0 + j) * HID + o] = accB[j];
        }
    }
}

// h1 rows 0..N-1: h1[j] = A[src[j]] + B[dst[j]]
__global__ void k_h1(const int* __restrict__ src, const int* __restrict__ dst, int Ncur) {
    int t = blockIdx.x * blockDim.x + threadIdx.x;
    if (t >= Ncur * HID) return;
    int j = t >> 7, f = t & 127;
    g_h1[t] = g_A[src[j] * HID + f] + g_B[dst[j] * HID + f];
}

// agg1[i] = sum over CSR bucket i of norm * h1[src]
__global__ void __launch_bounds__(128) k_agg1() {
    int i = blockIdx.x, f = threadIdx.x;
    int lo = g_rowptr[i], hi = g_rowptr[i + 1];
    float acc = 0.f;
    int k = lo;
    for (; k + 4 <= hi; k += 4) {
        int s0 = g_csrc[k], s1 = g_csrc[k + 1], s2 = g_csrc[k + 2], s3 = g_csrc[k + 3];
        float n0 = g_cnorm[k], n1 = g_cnorm[k + 1], n2 = g_cnorm[k + 2], n3 = g_cnorm[k + 3];
        float v0 = g_h1[s0 * HID + f], v1 = g_h1[s1 * HID + f];
        float v2 = g_h1[s2 * HID + f], v3 = g_h1[s3 * HID + f];
        acc = fmaf(n0, v0, acc); acc = fmaf(n1, v1, acc);
        acc = fmaf(n2, v2, acc); acc = fmaf(n3, v3, acc);
    }
    for (; k < hi; k++) acc = fmaf(g_cnorm[k], g_h1[g_csrc[k] * HID + f], acc);
    g_agg1[i * HID + f] = acc;
}

// BN stats: per-block partial sum/sumsq over pre-activation rows (fixed order)
__global__ void __launch_bounds__(128) k_bnstats(const int* __restrict__ src,
                                                 const int* __restrict__ dst,
                                                 const float* __restrict__ b1,
                                                 int Ncur, int Ecur) {
    int f = threadIdx.x;
    float bb = b1[f];
    float s_ = 0.f, q_ = 0.f;
    int stride = gridDim.x;
    int i = blockIdx.x;
    int sn = (i < Ecur) ? src[i] : 0, dn = (i < Ecur) ? dst[i] : 0;
    while (i < Ecur) {
        int inext = i + stride;
        float vA = g_A[sn * HID + f];
        float vB = g_B[dn * HID + f];
        float ag = 0.f, idg = 1.f;
        if (i < Ncur) { ag = g_agg1[i * HID + f]; idg = g_invdeg[i]; }
        if (inext < Ecur) { sn = src[inext]; dn = dst[inext]; }
        float v = idg * (vA + vB) + ag + bb;
        s_ += v;
        q_ = fmaf(v, v, q_);
        i = inext;
    }
    g_part[blockIdx.x * (2 * HID) + f]       = s_;
    g_part[blockIdx.x * (2 * HID) + HID + f] = q_;
}

// finalize BN: a = gamma*istd, c = beta - mu*a   (fixed-order reduce -> deterministic)
__global__ void k_bnred(const float* __restrict__ gamma, const float* __restrict__ beta, int Ecur) {
    int f = threadIdx.x;
    float s = 0.f, q = 0.f;
    for (int b = 0; b < STATS_BLOCKS; b++) {
        s += g_part[b * (2 * HID) + f];
        q += g_part[b * (2 * HID) + HID + f];
    }
    float invE = 1.0f / (float)Ecur;
    float mu  = s * invE;
    float var = q * invE - mu * mu;
    float istd = rsqrtf(var + 1e-5f);
    float a = gamma[f] * istd;
    g_af[f] = a;
    g_cf[f] = beta[f] - mu * a;
}

// W2l = Wl @ W2 ; cvec = Wl@b2 + bl
__global__ void k_w2l(const float* __restrict__ Wl, const float* __restrict__ W2,
                      const float* __restrict__ b2, const float* __restrict__ bl) {
    int t = blockIdx.x * blockDim.x + threadIdx.x;  // 8192 threads
    int o = t >> 7, f = t & 127;
    float acc = 0.f;
#pragma unroll
    for (int m = 0; m < 64; m++) acc = fmaf(Wl[o * 64 + m], W2[m * HID + f], acc);
    g_W2l[t] = acc;
    if (t < 64) {
        float cv = 0.f;
        for (int m = 0; m < 64; m++) cv = fmaf(Wl[t * 64 + m], b2[m], cv);
        g_cvec[t] = cv + bl[t];
    }
}

// wz[j] = W2l @ relu(bn(pre_j)) for j < N   (needed by aggregation 2)
__global__ void __launch_bounds__(128) k_z(const int* __restrict__ src,
                                           const int* __restrict__ dst,
                                           const float* __restrict__ b1, int Ncur) {
    int f = threadIdx.x;
    float bb = b1[f], af = g_af[f], cf = g_cf[f];
    int o = f & 63, h = f >> 6;
    float wreg[64];
#pragma unroll
    for (int k = 0; k < 64; k++) wreg[k] = g_W2l[o * HID + h * 64 + k];
    __shared__ __align__(16) float rsh[HID];
    __shared__ float ps[64];
    for (int j = blockIdx.x; j < Ncur; j += gridDim.x) {
        int s = src[j], d = dst[j];
        float v = g_A[s * HID + f] + g_B[d * HID + f];
        v = g_invdeg[j] * v + g_agg1[j * HID + f] + bb;
        rsh[f] = fmaxf(fmaf(af, v, cf), 0.f);
        __syncthreads();
        const float4* r4 = (const float4*)(rsh + h * 64);
        float a0 = 0.f, a1 = 0.f, a2 = 0.f, a3 = 0.f;
#pragma unroll
        for (int k = 0; k < 16; k++) {
            float4 rv = r4[k];
            a0 = fmaf(wreg[4 * k + 0], rv.x, a0);
            a1 = fmaf(wreg[4 * k + 1], rv.y, a1);
            a2 = fmaf(wreg[4 * k + 2], rv.z, a2);
            a3 = fmaf(wreg[4 * k + 3], rv.w, a3);
        }
        float part = (a0 + a1) + (a2 + a3);
        if (h) ps[o] = part;
        __syncthreads();
        if (!h) g_wz[j * FOUT + o] = part + ps[o];
        __syncthreads();
    }
}

// wa2[i] = sum over bucket i of norm * wz[src]
__global__ void __launch_bounds__(64) k_agg2() {
    int i = blockIdx.x, f = threadIdx.x;
    int lo = g_rowptr[i], hi = g_rowptr[i + 1];
    float acc = 0.f;
    int k = lo;
    for (; k + 4 <= hi; k += 4) {
        int s0 = g_csrc[k], s1 = g_csrc[k + 1], s2 = g_csrc[k + 2], s3 = g_csrc[k + 3];
        float n0 = g_cnorm[k], n1 = g_cnorm[k + 1], n2 = g_cnorm[k + 2], n3 = g_cnorm[k + 3];
        float v0 = g_wz[s0 * FOUT + f], v1 = g_wz[s1 * FOUT + f];
        float v2 = g_wz[s2 * FOUT + f], v3 = g_wz[s3 * FOUT + f];
        acc = fmaf(n0, v0, acc); acc = fmaf(n1, v1, acc);
        acc = fmaf(n2, v2, acc); acc = fmaf(n3, v3, acc);
    }
    for (; k < hi; k++) acc = fmaf(g_cnorm[k], g_wz[g_csrc[k] * FOUT + f], acc);
    g_wa2[i * FOUT + f] = acc;
}

// rows i < N: y = invdeg*wz + wa2 + cvec  (pure elementwise)
__global__ void k_small(const float* __restrict__ cutp, float* __restrict__ outp,
                        float* __restrict__ outr, int Ncur) {
    int t = blockIdx.x * blockDim.x + threadIdx.x;
    if (t >= Ncur * FOUT) return;
    int i = t >> 6, o = t & 63;
    float y = g_invdeg[i] * g_wz[t] + g_wa2[t] + g_cvec[o];
    float p = 1.0f / (1.0f + expf(-y));
    outp[t] = p;
    outr[t] = (p < *cutp) ? 0.0f : 1.0f;
}

// rows i in [N, E): no aggregation terms; full matvec + sigmoid + threshold
__global__ void __launch_bounds__(128) k_final(const int* __restrict__ src,
                                               const int* __restrict__ dst,
                                               const float* __restrict__ b1,
                                               const float* __restrict__ cutp,
                                               float* __restrict__ outp,
                                               float* __restrict__ outr,
                                               int Ncur, int Ecur) {
    int f = threadIdx.x;
    float bb = b1[f], af = g_af[f], cf = g_cf[f];
    int o = f & 63, h = f >> 6;
    float wreg[64];
#pragma unroll
    for (int k = 0; k < 64; k++) wreg[k] = g_W2l[o * HID + h * 64 + k];
    float cv  = g_cvec[o];
    float cut = *cutp;
    __shared__ __align__(16) float rsh[HID];
    __shared__ float ps[64];
    int i = Ncur + blockIdx.x;
    if (i >= Ecur) return;
    int s = src[i], d = dst[i];
    while (i < Ecur) {
        int inext = i + gridDim.x;
        float vA = g_A[s * HID + f];
        float vB = g_B[d * HID + f];
        if (inext < Ecur) { s = src[inext]; d = dst[inext]; }
        float v = vA + vB + bb;
        rsh[f] = fmaxf(fmaf(af, v, cf), 0.f);
        __syncthreads();
        const float4* r4 = (const float4*)(rsh + h * 64);
        float a0 = 0.f, a1 = 0.f, a2 = 0.f, a3 = 0.f;
#pragma unroll
        for (int k = 0; k < 16; k++) {
            float4 rv = r4[k];
            a0 = fmaf(wreg[4 * k + 0], rv.x, a0);
            a1 = fmaf(wreg[4 * k + 1], rv.y, a1);
            a2 = fmaf(wreg[4 * k + 2], rv.z, a2);
            a3 = fmaf(wreg[4 * k + 3], rv.w, a3);
        }
        float part = (a0 + a1) + (a2 + a3);
        if (h) ps[o] = part;
        __syncthreads();
        if (!h) {
            float y = (part + ps[o]) + cv;
            float p = 1.0f / (1.0f + expf(-y));
            size_t off = (size_t)i * FOUT + o;
            outp[off] = p;
            outr[off] = (p < cut) ? 0.0f : 1.0f;
        }
        __syncthreads();
        i = inext;
    }
}

// ---------------- launch ----------------
extern "C" void kernel_launch(void* const* d_in, const int* in_sizes, int n_in,
                              void* d_out, int out_size) {
    const float* x     = (const float*)d_in[0];
    const int*   edge  = (const int*)d_in[1];
    const float* W1    = (const float*)d_in[2];
    const float* b1    = (const float*)d_in[3];
    const float* gamma = (const float*)d_in[4];
    const float* beta  = (const float*)d_in[5];
    const float* W2    = (const float*)d_in[6];
    const float* b2    = (const float*)d_in[7];
    const float* Wl    = (const float*)d_in[8];
    const float* bl    = (const float*)d_in[9];
    const float* cut   = (const float*)d_in[10];

    int Ncur = in_sizes[0] / FIN;
    int Ecur = in_sizes[1] / 2;
    if (Ncur > NMAX || Ecur > EMAX || Ncur <= 0 || Ecur <= 0) return;

    const int* src = edge;
    const int* dst = edge + Ecur;
    float* outp = (float*)d_out;
    float* outr = outp + (size_t)out_size / 2;

    k_zero <<<(Ncur + 255) / 256, 256>>>(Ncur);
    k_count<<<(Ecur + 255) / 256, 256>>>(dst, Ecur);
    k_dis  <<<(Ncur + 255) / 256, 256>>>(Ncur);
    k_scan <<<1, 1024>>>(Ncur);
    k_fill <<<(Ecur + 255) / 256, 256>>>(dst, Ecur);
    k_sort <<<(Ncur + 127) / 128, 128>>>(src, Ncur);
    k_ab   <<<(Ncur + 15) / 16, 128>>>(x, W1, Ncur);
    k_h1   <<<(Ncur * HID + 255) / 256, 256>>>(src, dst, Ncur);
    k_agg1 <<<Ncur, 128>>>();
    k_bnstats<<<STATS_BLOCKS, 128>>>(src, dst, b1, Ncur, Ecur);
    k_bnred<<<1, 128>>>(gamma, beta, Ecur);
    k_w2l  <<<64, 128>>>(Wl, W2, b2, bl);
    {
        int g = Ncur < 2048 ? Ncur : 2048;
        k_z<<<g, 128>>>(src, dst, b1, Ncur);
    }
    k_agg2 <<<Ncur, 64>>>();
    k_small<<<(Ncur * FOUT + 255) / 256, 256>>>(cut, outp, outr, Ncur);
    {
        int rows = Ecur - Ncur;
        int g = rows < 4096 ? rows : 4096;
        if (g > 0)
            k_final<<<g, 128>>>(src, dst, b1, cut, outp, outr, Ncur, Ecur);
    }
}